// round 8
// baseline (speedup 1.0000x reference)
#include <cuda_runtime.h>
#include <cstdint>

// Problem constants
#define BB   4
#define TT   2048
#define NC   4096
#define AA   8
#define SINK_ITERS 20
#define EPS_ 1e-5f

// logits tiling (identical to the best-measured R3 config)
#define TOK    32            // tokens per CTA
#define DT     128           // d-tile
#define KSPLIT 8
#define DPART  (NC / KSPLIT) // 512
#define TILES  (DPART / DT)  // 4
#define XROWF  136           // x smem row stride (floats)
#define PROWF  28            // phi smem row stride (floats)
#define PARTW  28            // partial row: 24 logits + ssq + pad

#define XT (TOK * XROWF)     // 4352 floats
#define PT (DT * PROWF)      // 3584 floats
#define BUFF (XT + PT)       // 7936 floats
#define SMEM_BYTES (2 * BUFF * 4)

#define NCHUNK 4
#define TOKCH  (BB * TT / NCHUNK)        // 2048 tokens per chunk
#define TILCH  (TOKCH / TOK)             // 64 token-tiles per chunk

// ---------------- scratch ----------------
__device__ __align__(16) float g_buf[AA * NC * 24];                 // folded phi [a][d][24]
__device__ __align__(16) float part_buf[KSPLIT * BB * TT * PARTW];  // 7.3 MB
__device__ __align__(16) float W_buf[BB * TT * 16];

// ---------------- helpers ----------------
typedef unsigned long long ull;
__device__ __forceinline__ void ffma2(ull& d, ull a, ull b) {
    asm("fma.rn.f32x2 %0, %1, %2, %0;" : "+l"(d) : "l"(a), "l"(b));
}
__device__ __forceinline__ void fadd2(ull& d, ull a, ull b) {
    asm("add.rn.f32x2 %0, %1, %2;" : "=l"(d) : "l"(a), "l"(b));
}
__device__ __forceinline__ ull dup2(float v) {
    ull r; asm("mov.b64 %0, {%1, %1};" : "=l"(r) : "f"(v)); return r;
}
__device__ __forceinline__ void unpack2(ull u, float& lo, float& hi) {
    asm("mov.b64 {%0, %1}, %2;" : "=f"(lo), "=f"(hi) : "l"(u));
}
__device__ __forceinline__ void cp16(uint32_t dst, const void* src) {
    asm volatile("cp.async.cg.shared.global [%0], [%1], 16;" :: "r"(dst), "l"(src));
}

// ---------------- kernel 1: fold alpha*w*phi -> g_buf[a][d][24] ----------------
// 1 float4 of output per thread: idx = ad*6 + c
__global__ void fold_k(const float* __restrict__ wnorm,
                       const float* __restrict__ ppre, const float* __restrict__ ppost,
                       const float* __restrict__ pres,
                       const float* __restrict__ apre, const float* __restrict__ apost,
                       const float* __restrict__ ares) {
    int idx = blockIdx.x * 128 + threadIdx.x;
    if (idx >= AA * NC * 6) return;
    int c = idx % 6;
    int ad = idx / 6;
    int a = ad >> 12;
    float wv = wnorm[ad];
    float coef = ((c == 0) ? apre[a] : (c == 1) ? apost[a] : ares[a]) * wv;
    float4 v = (c == 0) ? ((const float4*)ppre)[ad]
             : (c == 1) ? ((const float4*)ppost)[ad]
                        : ((const float4*)pres)[(size_t)ad * 4 + (c - 2)];
    ((float4*)g_buf)[idx] = make_float4(coef * v.x, coef * v.y, coef * v.z, coef * v.w);
}

// ---------------- kernel 2: partial logits (R3-identical, chunked + PDL trigger) ----------------
// grid = 512 per chunk: blockIdx.x = tt_local*KSPLIT + ks (KSPLIT low bits). 128 threads:
//   s = tid&7 (d-slice), tg = (tid>>3)&7 (token group: tokens tg+8j), kh = tid>>6 (k half)
__global__ void __launch_bounds__(128, 3)
logits_k(const float* __restrict__ x, const int* __restrict__ aidx, int chunk) {
    cudaTriggerProgrammaticLaunchCompletion();   // allow PDL successor (out_k) to start

    extern __shared__ float smem[];
    const int tid = threadIdx.x;
    const int ks = blockIdx.x & (KSPLIT - 1);
    const int tt = (blockIdx.x >> 3) + chunk * TILCH;
    const int b  = tt >> 6;
    const int t0 = (tt & 63) * TOK;
    const int aid = aidx[b];
    const int s = tid & 7, tg = (tid >> 3) & 7, kh = tid >> 6;

    const float* xb = x + ((size_t)(b * TT + t0)) * NC + ks * DPART;
    const float* gb = g_buf + ((size_t)aid * NC + ks * DPART) * 24;

    uint32_t sbase = (uint32_t)__cvta_generic_to_shared(smem);
    const uint32_t xbase[2] = { sbase,          sbase + BUFF * 4 };
    const uint32_t pbase[2] = { sbase + XT * 4, sbase + (BUFF + XT) * 4 };

    ull acc[24];
#pragma unroll
    for (int k = 0; k < 24; ++k) acc[k] = 0ull;
    ull ssq[4] = {0ull, 0ull, 0ull, 0ull};

    auto copy_tile = [&](int tile, int bi) {
        const int d0 = tile * DT;
#pragma unroll
        for (int i2 = 0; i2 < 8; ++i2) {            // x: 1024 float4
            int f = i2 * 128 + tid;
            int tok = f >> 5, q = f & 31;
            cp16(xbase[bi] + tok * (XROWF * 4) + q * 16,
                 xb + (size_t)tok * NC + d0 + q * 4);
        }
#pragma unroll
        for (int i2 = 0; i2 < 6; ++i2) {            // phi: 768 float4
            int f = i2 * 128 + tid;
            int d = f / 6, c = f - d * 6;
            cp16(pbase[bi] + d * (PROWF * 4) + c * 16,
                 gb + (size_t)(d0 + d) * 24 + c * 4);
        }
        asm volatile("cp.async.commit_group;");
    };

    copy_tile(0, 0);

    for (int t = 0; t < TILES; ++t) {
        if (t + 1 < TILES) {
            copy_tile(t + 1, (t + 1) & 1);
            asm volatile("cp.async.wait_group 1;");
        } else {
            asm volatile("cp.async.wait_group 0;");
        }
        __syncthreads();

        const float* xs = smem + (t & 1) * BUFF;
        const float* ps = xs + XT;
        const float* xr0 = xs + (tg     ) * XROWF;
        const float* xr1 = xs + (tg +  8) * XROWF;
        const float* xr2 = xs + (tg + 16) * XROWF;
        const float* xr3 = xs + (tg + 24) * XROWF;

#pragma unroll 4
        for (int i = 0; i < 16; ++i) {
            const int dd = i * 8 + s;
            ull x0 = dup2(xr0[dd]);
            ull x1 = dup2(xr1[dd]);
            ull x2 = dup2(xr2[dd]);
            ull x3 = dup2(xr3[dd]);
            if (kh == 0) {
                ffma2(ssq[0], x0, x0); ffma2(ssq[1], x1, x1);
                ffma2(ssq[2], x2, x2); ffma2(ssq[3], x3, x3);
            }
            const ulonglong2* pp = (const ulonglong2*)(ps + dd * PROWF + kh * 12);
            ulonglong2 pA = pp[0], pB = pp[1], pC = pp[2];
            ffma2(acc[0],  x0, pA.x); ffma2(acc[6],  x1, pA.x);
            ffma2(acc[12], x2, pA.x); ffma2(acc[18], x3, pA.x);
            ffma2(acc[1],  x0, pA.y); ffma2(acc[7],  x1, pA.y);
            ffma2(acc[13], x2, pA.y); ffma2(acc[19], x3, pA.y);
            ffma2(acc[2],  x0, pB.x); ffma2(acc[8],  x1, pB.x);
            ffma2(acc[14], x2, pB.x); ffma2(acc[20], x3, pB.x);
            ffma2(acc[3],  x0, pB.y); ffma2(acc[9],  x1, pB.y);
            ffma2(acc[15], x2, pB.y); ffma2(acc[21], x3, pB.y);
            ffma2(acc[4],  x0, pC.x); ffma2(acc[10], x1, pC.x);
            ffma2(acc[16], x2, pC.x); ffma2(acc[22], x3, pC.x);
            ffma2(acc[5],  x0, pC.y); ffma2(acc[11], x1, pC.y);
            ffma2(acc[17], x2, pC.y); ffma2(acc[23], x3, pC.y);
        }
        __syncthreads();
    }

    // reduce over the 8 d-slices (lane bits 0..2)
#pragma unroll
    for (int k = 0; k < 24; ++k) {
#pragma unroll
        for (int m = 1; m < 8; m <<= 1) {
            ull o = __shfl_xor_sync(0xffffffffu, acc[k], m);
            fadd2(acc[k], acc[k], o);
        }
    }
    if (kh == 0) {
#pragma unroll
        for (int j = 0; j < 4; ++j) {
#pragma unroll
            for (int m = 1; m < 8; m <<= 1) {
                ull o = __shfl_xor_sync(0xffffffffu, ssq[j], m);
                fadd2(ssq[j], ssq[j], o);
            }
        }
    }

    if (s == 0) {
        const int tbase = b * TT + t0 + tg;
#pragma unroll
        for (int j = 0; j < 4; ++j) {
            float* pa = part_buf + ((size_t)ks * (BB * TT) + tbase + 8 * j) * PARTW;
#pragma unroll
            for (int c = 0; c < 6; ++c) {
                float lo, hi; unpack2(acc[j * 6 + c], lo, hi);
                pa[kh * 12 + 2 * c]     = lo;
                pa[kh * 12 + 2 * c + 1] = hi;
            }
            if (kh == 0) {
                float lo, hi; unpack2(ssq[j], lo, hi);
                pa[24] = lo;   // duplicated lanes: lo == hi == true sum
            }
        }
    }
}

// ---------------- kernel 3: finalize (reduce splits, sinkhorn -> W), chunked ----------------
__global__ void finalize_k(const float* __restrict__ bpre, const float* __restrict__ bpost,
                           const float* __restrict__ bres, const int* __restrict__ aidx,
                           int chunk) {
    const int t = chunk * TOKCH + blockIdx.x * 128 + threadIdx.x;
    const int aid = aidx[t >> 11];

    float a[24];
#pragma unroll
    for (int k = 0; k < 24; ++k) a[k] = 0.0f;
    float ssq = 0.0f;
#pragma unroll
    for (int ks = 0; ks < KSPLIT; ++ks) {
        const float4* p = (const float4*)(part_buf + ((size_t)ks * (BB * TT) + t) * PARTW);
#pragma unroll
        for (int q = 0; q < 6; ++q) {
            float4 v = p[q];
            a[q * 4 + 0] += v.x; a[q * 4 + 1] += v.y;
            a[q * 4 + 2] += v.z; a[q * 4 + 3] += v.w;
        }
        ssq += p[6].x;
    }
    float rinv = rsqrtf(ssq * (1.0f / 4096.0f) + EPS_);

    float hpre[4], hpost[4];
#pragma unroll
    for (int n = 0; n < 4; ++n)
        hpre[n] = 1.0f / (1.0f + expf(-(a[n] * rinv + bpre[aid * 4 + n])));
#pragma unroll
    for (int n = 0; n < 4; ++n)
        hpost[n] = 2.0f / (1.0f + expf(-(a[4 + n] * rinv + bpost[aid * 4 + n])));

    float m[16];
#pragma unroll
    for (int ij = 0; ij < 16; ++ij)
        m[ij] = expf(a[8 + ij] * rinv + bres[aid * 16 + ij]);

    for (int it = 0; it < SINK_ITERS; ++it) {
#pragma unroll
        for (int i = 0; i < 4; ++i) {
            float r = 1.0f / (m[i * 4] + m[i * 4 + 1] + m[i * 4 + 2] + m[i * 4 + 3]);
            m[i * 4] *= r; m[i * 4 + 1] *= r; m[i * 4 + 2] *= r; m[i * 4 + 3] *= r;
        }
#pragma unroll
        for (int j = 0; j < 4; ++j) {
            float r = 1.0f / (m[j] + m[4 + j] + m[8 + j] + m[12 + j]);
            m[j] *= r; m[4 + j] *= r; m[8 + j] *= r; m[12 + j] *= r;
        }
    }

    float4* wd = (float4*)(W_buf + (size_t)t * 16);
#pragma unroll
    for (int i = 0; i < 4; ++i)
        wd[i] = make_float4(m[i * 4 + 0] + hpost[i] * hpre[0],
                            m[i * 4 + 1] + hpost[i] * hpre[1],
                            m[i * 4 + 2] + hpost[i] * hpre[2],
                            m[i * 4 + 3] + hpost[i] * hpre[3]);
}

// ---------------- kernel 4: out[token] = W @ x[token], chunked ----------------
// Launched with PDL (programmaticStreamSerializationAllowed): overlaps the NEXT logits chunk.
// Reads nothing its PDL-primary writes (W chunk was finalized 2 launches earlier).
__global__ void out_k(const float* __restrict__ x, float* __restrict__ out, int chunk) {
    const int token = chunk * TOKCH + blockIdx.x;
    __shared__ float sW[16];
    if (threadIdx.x < 16) sW[threadIdx.x] = W_buf[(size_t)token * 16 + threadIdx.x];
    __syncthreads();
    const float4* xr = (const float4*)(x + (size_t)token * NC);
    float4* orow = (float4*)(out + (size_t)token * NC);
    const int c = threadIdx.x;
    float4 xv0 = xr[c], xv1 = xr[256 + c], xv2 = xr[512 + c], xv3 = xr[768 + c];
#pragma unroll
    for (int i = 0; i < 4; ++i) {
        float w0 = sW[i * 4], w1 = sW[i * 4 + 1], w2 = sW[i * 4 + 2], w3 = sW[i * 4 + 3];
        float4 o;
        o.x = w0 * xv0.x + w1 * xv1.x + w2 * xv2.x + w3 * xv3.x;
        o.y = w0 * xv0.y + w1 * xv1.y + w2 * xv2.y + w3 * xv3.y;
        o.z = w0 * xv0.z + w1 * xv1.z + w2 * xv2.z + w3 * xv3.z;
        o.w = w0 * xv0.w + w1 * xv1.w + w2 * xv2.w + w3 * xv3.w;
        orow[i * 256 + c] = o;
    }
}

// ---------------- launch ----------------
extern "C" void kernel_launch(void* const* d_in, const int* in_sizes, int n_in,
                              void* d_out, int out_size) {
    const float* x     = (const float*)d_in[0];
    const float* wnorm = (const float*)d_in[1];
    const float* ppre  = (const float*)d_in[2];
    const float* ppost = (const float*)d_in[3];
    const float* pres  = (const float*)d_in[4];
    const float* bpre  = (const float*)d_in[5];
    const float* bpost = (const float*)d_in[6];
    const float* bres  = (const float*)d_in[7];
    const float* apre  = (const float*)d_in[8];
    const float* apost = (const float*)d_in[9];
    const float* ares  = (const float*)d_in[10];
    const int*   aidx  = (const int*)d_in[11];
    float* out = (float*)d_out;

    cudaFuncSetAttribute(logits_k, cudaFuncAttributeMaxDynamicSharedMemorySize, SMEM_BYTES);

    // PDL launch config for out_k chunks
    cudaLaunchAttribute pdl_attr[1];
    pdl_attr[0].id = cudaLaunchAttributeProgrammaticStreamSerialization;
    pdl_attr[0].val.programmaticStreamSerializationAllowed = 1;
    cudaLaunchConfig_t ocfg = {};
    ocfg.gridDim = dim3(TOKCH, 1, 1);
    ocfg.blockDim = dim3(256, 1, 1);
    ocfg.dynamicSmemBytes = 0;
    ocfg.stream = 0;
    ocfg.attrs = pdl_attr;
    ocfg.numAttrs = 1;

    fold_k<<<(AA * NC * 6 + 127) / 128, 128>>>(wnorm, ppre, ppost, pres, apre, apost, ares);

    // Pipeline: L0,F0, [L1,O0(PDL)],F1, [L2,O1(PDL)],F2, [L3,O2(PDL)],F3, O3
    logits_k<<<TILCH * KSPLIT, 128, SMEM_BYTES>>>(x, aidx, 0);
    finalize_k<<<TOKCH / 128, 128>>>(bpre, bpost, bres, aidx, 0);
    for (int c = 0; c < NCHUNK - 1; ++c) {
        logits_k<<<TILCH * KSPLIT, 128, SMEM_BYTES>>>(x, aidx, c + 1);
        cudaLaunchKernelEx(&ocfg, out_k, x, out, c);       // overlaps logits chunk c+1
        finalize_k<<<TOKCH / 128, 128>>>(bpre, bpost, bres, aidx, c + 1);
    }
    out_k<<<TOKCH, 256>>>(x, out, NCHUNK - 1);
}

// round 9
// speedup vs baseline: 1.1033x; 1.1033x over previous
#include <cuda_runtime.h>
#include <cstdint>

// Problem constants
#define BB   4
#define TT   2048
#define NC   4096
#define AA   8
#define SINK_ITERS 20
#define EPS_ 1e-5f

// logits tiling: one d-tile per CTA, barrier-free main loop
#define TOK    32             // tokens per CTA
#define KSPLIT 32
#define DPART  (NC / KSPLIT)  // 128 = exactly one tile
#define XROWF  136            // x smem row stride (floats)
#define PROWF  28             // phi smem row stride (floats)
#define PARTW  28             // partial row: 24 logits + ssq + pad

#define XT (TOK * XROWF)      // 4352 floats
#define PT (DPART * PROWF)    // 3584 floats
#define BUFF (XT + PT)        // 7936 floats = 31744 B (single buffer)

// ---------------- scratch ----------------
__device__ __align__(16) float g_buf[AA * NC * 24];                 // folded phi [a][d][24]
__device__ __align__(16) float part_buf[KSPLIT * BB * TT * PARTW];  // 29.4 MB
__device__ __align__(16) float W_buf[BB * TT * 16];

// ---------------- helpers ----------------
typedef unsigned long long ull;
__device__ __forceinline__ void ffma2(ull& d, ull a, ull b) {
    asm("fma.rn.f32x2 %0, %1, %2, %0;" : "+l"(d) : "l"(a), "l"(b));
}
__device__ __forceinline__ void fadd2(ull& d, ull a, ull b) {
    asm("add.rn.f32x2 %0, %1, %2;" : "=l"(d) : "l"(a), "l"(b));
}
__device__ __forceinline__ ull dup2(float v) {
    ull r; asm("mov.b64 %0, {%1, %1};" : "=l"(r) : "f"(v)); return r;
}
__device__ __forceinline__ void unpack2(ull u, float& lo, float& hi) {
    asm("mov.b64 {%0, %1}, %2;" : "=f"(lo), "=f"(hi) : "l"(u));
}
__device__ __forceinline__ void cp16(uint32_t dst, const void* src) {
    asm volatile("cp.async.cg.shared.global [%0], [%1], 16;" :: "r"(dst), "l"(src));
}

// ---------------- kernel 1: fold alpha*w*phi -> g_buf[a][d][24] ----------------
__global__ void fold_k(const float* __restrict__ wnorm,
                       const float* __restrict__ ppre, const float* __restrict__ ppost,
                       const float* __restrict__ pres,
                       const float* __restrict__ apre, const float* __restrict__ apost,
                       const float* __restrict__ ares) {
    int idx = blockIdx.x * 128 + threadIdx.x;    // (a,d)*6 + c
    if (idx >= AA * NC * 6) return;
    int c = idx % 6;
    int ad = idx / 6;
    int a = ad >> 12;
    float wv = wnorm[ad];
    float coef = ((c == 0) ? apre[a] : (c == 1) ? apost[a] : ares[a]) * wv;
    float4 v = (c == 0) ? ((const float4*)ppre)[ad]
             : (c == 1) ? ((const float4*)ppost)[ad]
                        : ((const float4*)pres)[(size_t)ad * 4 + (c - 2)];
    ((float4*)g_buf)[idx] = make_float4(coef * v.x, coef * v.y, coef * v.z, coef * v.w);
}

// ---------------- kernel 2: partial logits — single tile, no in-loop barriers ----------------
// grid = 8192: blockIdx.x = tt*KSPLIT + ks. 128 threads:
//   s = tid&7 (d-slice), tg = (tid>>3)&7 (tokens tg+8j, j=0..3), kh = tid>>6 (k half)
__global__ void __launch_bounds__(128, 4)
logits_k(const float* __restrict__ x, const int* __restrict__ aidx) {
    __shared__ __align__(16) float smem[BUFF];

    const int tid = threadIdx.x;
    const int ks = blockIdx.x & (KSPLIT - 1);
    const int tt = blockIdx.x >> 5;              // token tile 0..255
    const int b  = tt >> 6;
    const int t0 = (tt & 63) * TOK;
    const int aid = aidx[b];
    const int s = tid & 7, tg = (tid >> 3) & 7, kh = tid >> 6;

    const float* xb = x + ((size_t)(b * TT + t0)) * NC + ks * DPART;
    const float* gb = g_buf + ((size_t)aid * NC + ks * DPART) * 24;

    uint32_t sbase = (uint32_t)__cvta_generic_to_shared(smem);
    const uint32_t xbase = sbase;
    const uint32_t pbase = sbase + XT * 4;

    // one-shot async copy of the whole working set
#pragma unroll
    for (int i2 = 0; i2 < 8; ++i2) {             // x: 1024 float4 (32 tok x 128 d)
        int f = i2 * 128 + tid;
        int tok = f >> 5, q = f & 31;
        cp16(xbase + tok * (XROWF * 4) + q * 16, xb + (size_t)tok * NC + q * 4);
    }
#pragma unroll
    for (int i2 = 0; i2 < 6; ++i2) {             // phi: 768 float4 (128 d x 24 k)
        int f = i2 * 128 + tid;
        int d = f / 6, c = f - d * 6;
        cp16(pbase + d * (PROWF * 4) + c * 16, gb + (size_t)d * 24 + c * 4);
    }
    asm volatile("cp.async.commit_group;");

    ull acc[24];
#pragma unroll
    for (int k = 0; k < 24; ++k) acc[k] = 0ull;
    ull ssq[4] = {0ull, 0ull, 0ull, 0ull};

    asm volatile("cp.async.wait_group 0;");
    __syncthreads();                              // the only barrier

    const float* xs = smem;
    const float* ps = smem + XT;
    const float* xr0 = xs + (tg     ) * XROWF;
    const float* xr1 = xs + (tg +  8) * XROWF;
    const float* xr2 = xs + (tg + 16) * XROWF;
    const float* xr3 = xs + (tg + 24) * XROWF;

#pragma unroll 4
    for (int i = 0; i < 16; ++i) {
        const int dd = i * 8 + s;
        ull x0 = dup2(xr0[dd]);
        ull x1 = dup2(xr1[dd]);
        ull x2 = dup2(xr2[dd]);
        ull x3 = dup2(xr3[dd]);
        if (kh == 0) {
            ffma2(ssq[0], x0, x0); ffma2(ssq[1], x1, x1);
            ffma2(ssq[2], x2, x2); ffma2(ssq[3], x3, x3);
        }
        const ulonglong2* pp = (const ulonglong2*)(ps + dd * PROWF + kh * 12);
        ulonglong2 pA = pp[0], pB = pp[1], pC = pp[2];
        ffma2(acc[0],  x0, pA.x); ffma2(acc[6],  x1, pA.x);
        ffma2(acc[12], x2, pA.x); ffma2(acc[18], x3, pA.x);
        ffma2(acc[1],  x0, pA.y); ffma2(acc[7],  x1, pA.y);
        ffma2(acc[13], x2, pA.y); ffma2(acc[19], x3, pA.y);
        ffma2(acc[2],  x0, pB.x); ffma2(acc[8],  x1, pB.x);
        ffma2(acc[14], x2, pB.x); ffma2(acc[20], x3, pB.x);
        ffma2(acc[3],  x0, pB.y); ffma2(acc[9],  x1, pB.y);
        ffma2(acc[15], x2, pB.y); ffma2(acc[21], x3, pB.y);
        ffma2(acc[4],  x0, pC.x); ffma2(acc[10], x1, pC.x);
        ffma2(acc[16], x2, pC.x); ffma2(acc[22], x3, pC.x);
        ffma2(acc[5],  x0, pC.y); ffma2(acc[11], x1, pC.y);
        ffma2(acc[17], x2, pC.y); ffma2(acc[23], x3, pC.y);
    }

    // reduce over the 8 d-slices (lane bits 0..2)
#pragma unroll
    for (int k = 0; k < 24; ++k) {
#pragma unroll
        for (int m = 1; m < 8; m <<= 1) {
            ull o = __shfl_xor_sync(0xffffffffu, acc[k], m);
            fadd2(acc[k], acc[k], o);
        }
    }
    if (kh == 0) {
#pragma unroll
        for (int j = 0; j < 4; ++j) {
#pragma unroll
            for (int m = 1; m < 8; m <<= 1) {
                ull o = __shfl_xor_sync(0xffffffffu, ssq[j], m);
                fadd2(ssq[j], ssq[j], o);
            }
        }
    }

    if (s == 0) {
        const int tbase = b * TT + t0 + tg;
#pragma unroll
        for (int j = 0; j < 4; ++j) {
            float* pa = part_buf + ((size_t)ks * (BB * TT) + tbase + 8 * j) * PARTW;
#pragma unroll
            for (int c = 0; c < 6; ++c) {
                float lo, hi; unpack2(acc[j * 6 + c], lo, hi);
                pa[kh * 12 + 2 * c]     = lo;
                pa[kh * 12 + 2 * c + 1] = hi;
            }
            if (kh == 0) {
                float lo, hi; unpack2(ssq[j], lo, hi);
                pa[24] = lo;   // duplicated lanes: lo == hi == true sum
            }
        }
    }
}

// ---------------- kernel 3: finalize (reduce 32 splits, sinkhorn -> W) ----------------
__global__ void finalize_k(const float* __restrict__ bpre, const float* __restrict__ bpost,
                           const float* __restrict__ bres, const int* __restrict__ aidx) {
    const int t = blockIdx.x * 128 + threadIdx.x;
    const int aid = aidx[t >> 11];

    float a[24];
#pragma unroll
    for (int k = 0; k < 24; ++k) a[k] = 0.0f;
    float ssq = 0.0f;
#pragma unroll 8
    for (int ks = 0; ks < KSPLIT; ++ks) {
        const float4* p = (const float4*)(part_buf + ((size_t)ks * (BB * TT) + t) * PARTW);
#pragma unroll
        for (int q = 0; q < 6; ++q) {
            float4 v = p[q];
            a[q * 4 + 0] += v.x; a[q * 4 + 1] += v.y;
            a[q * 4 + 2] += v.z; a[q * 4 + 3] += v.w;
        }
        ssq += p[6].x;
    }
    float rinv = rsqrtf(ssq * (1.0f / 4096.0f) + EPS_);

    float hpre[4], hpost[4];
#pragma unroll
    for (int n = 0; n < 4; ++n)
        hpre[n] = 1.0f / (1.0f + expf(-(a[n] * rinv + bpre[aid * 4 + n])));
#pragma unroll
    for (int n = 0; n < 4; ++n)
        hpost[n] = 2.0f / (1.0f + expf(-(a[4 + n] * rinv + bpost[aid * 4 + n])));

    float m[16];
#pragma unroll
    for (int ij = 0; ij < 16; ++ij)
        m[ij] = expf(a[8 + ij] * rinv + bres[aid * 16 + ij]);

    for (int it = 0; it < SINK_ITERS; ++it) {
#pragma unroll
        for (int i = 0; i < 4; ++i) {
            float r = 1.0f / (m[i * 4] + m[i * 4 + 1] + m[i * 4 + 2] + m[i * 4 + 3]);
            m[i * 4] *= r; m[i * 4 + 1] *= r; m[i * 4 + 2] *= r; m[i * 4 + 3] *= r;
        }
#pragma unroll
        for (int j = 0; j < 4; ++j) {
            float r = 1.0f / (m[j] + m[4 + j] + m[8 + j] + m[12 + j]);
            m[j] *= r; m[4 + j] *= r; m[8 + j] *= r; m[12 + j] *= r;
        }
    }

    float4* wd = (float4*)(W_buf + (size_t)t * 16);
#pragma unroll
    for (int i = 0; i < 4; ++i)
        wd[i] = make_float4(m[i * 4 + 0] + hpost[i] * hpre[0],
                            m[i * 4 + 1] + hpost[i] * hpre[1],
                            m[i * 4 + 2] + hpost[i] * hpre[2],
                            m[i * 4 + 3] + hpost[i] * hpre[3]);
}

// ---------------- kernel 4: out[token] = W @ x[token] ----------------
__global__ void out_k(const float* __restrict__ x, float* __restrict__ out) {
    const int token = blockIdx.x;
    __shared__ float sW[16];
    if (threadIdx.x < 16) sW[threadIdx.x] = W_buf[(size_t)token * 16 + threadIdx.x];
    __syncthreads();
    const float4* xr = (const float4*)(x + (size_t)token * NC);
    float4* orow = (float4*)(out + (size_t)token * NC);
    const int c = threadIdx.x;
    float4 xv0 = xr[c], xv1 = xr[256 + c], xv2 = xr[512 + c], xv3 = xr[768 + c];
#pragma unroll
    for (int i = 0; i < 4; ++i) {
        float w0 = sW[i * 4], w1 = sW[i * 4 + 1], w2 = sW[i * 4 + 2], w3 = sW[i * 4 + 3];
        float4 o;
        o.x = w0 * xv0.x + w1 * xv1.x + w2 * xv2.x + w3 * xv3.x;
        o.y = w0 * xv0.y + w1 * xv1.y + w2 * xv2.y + w3 * xv3.y;
        o.z = w0 * xv0.z + w1 * xv1.z + w2 * xv2.z + w3 * xv3.z;
        o.w = w0 * xv0.w + w1 * xv1.w + w2 * xv2.w + w3 * xv3.w;
        orow[i * 256 + c] = o;
    }
}

// ---------------- launch ----------------
extern "C" void kernel_launch(void* const* d_in, const int* in_sizes, int n_in,
                              void* d_out, int out_size) {
    const float* x     = (const float*)d_in[0];
    const float* wnorm = (const float*)d_in[1];
    const float* ppre  = (const float*)d_in[2];
    const float* ppost = (const float*)d_in[3];
    const float* pres  = (const float*)d_in[4];
    const float* bpre  = (const float*)d_in[5];
    const float* bpost = (const float*)d_in[6];
    const float* bres  = (const float*)d_in[7];
    const float* apre  = (const float*)d_in[8];
    const float* apost = (const float*)d_in[9];
    const float* ares  = (const float*)d_in[10];
    const int*   aidx  = (const int*)d_in[11];
    float* out = (float*)d_out;

    fold_k<<<(AA * NC * 6 + 127) / 128, 128>>>(wnorm, ppre, ppost, pres, apre, apost, ares);
    logits_k<<<(BB * TT / TOK) * KSPLIT, 128>>>(x, aidx);
    finalize_k<<<BB * TT / 128, 128>>>(bpre, bpost, bres, aidx);
    out_k<<<BB * TT, 256>>>(x, out);
}